// round 9
// baseline (speedup 1.0000x reference)
#include <cuda_runtime.h>
#include <cuda_bf16.h>
#include <cstdint>
#include <math.h>

#define D      128
#define NTOK   32768
#define KCODE  1024
#define TILEM  128
#define TILEN  128
#define NITER  8
#define PAD    132
#define TH_DDP 1.5e-4f   // margin on dd' = sc/2 - dot scale (dist scale: 3e-4)

// ---------------- device scratch ----------------
__device__ __align__(16) __nv_bfloat16 g_zh[NTOK * D];
__device__ __align__(16) __nv_bfloat16 g_ch[KCODE * D];
__device__ float  g_sz[NTOK];
__device__ float  g_sc[KCODE];
__device__ float  g_schalf[KCODE];
__device__ int    g_idx[NTOK];
__device__ int    g_cand[NTOK * 16];
__device__ int    g_fixlist[NTOK];
__device__ int    g_nfix;
__device__ double g_loss;

// ---------------- helpers ----------------
__device__ __forceinline__ uint32_t smem_u32(const void* p) {
    uint32_t a;
    asm("{ .reg .u64 t; cvta.to.shared.u64 t, %1; cvt.u32.u64 %0, t; }" : "=r"(a) : "l"(p));
    return a;
}
__device__ __forceinline__ void ldsm_x4(uint32_t* r, uint32_t a) {
    asm volatile("ldmatrix.sync.aligned.m8n8.x4.shared.b16 {%0,%1,%2,%3}, [%4];"
                 : "=r"(r[0]), "=r"(r[1]), "=r"(r[2]), "=r"(r[3]) : "r"(a));
}
__device__ __forceinline__ void mma16816(float* d, const uint32_t* a, const uint32_t* b) {
    asm volatile("mma.sync.aligned.m16n8k16.row.col.f32.bf16.bf16.f32 "
                 "{%0,%1,%2,%3},{%4,%5,%6,%7},{%8,%9},{%0,%1,%2,%3};"
                 : "+f"(d[0]), "+f"(d[1]), "+f"(d[2]), "+f"(d[3])
                 : "r"(a[0]), "r"(a[1]), "r"(a[2]), "r"(a[3]), "r"(b[0]), "r"(b[1]));
}
__device__ __forceinline__ void cp16(uint32_t dst, const void* src) {
    asm volatile("cp.async.cg.shared.global [%0], [%1], 16;" :: "r"(dst), "l"(src));
}
// branchless top-2 insert (2 FSETP + 6 SEL)
__device__ __forceinline__ void ins2(float& v0, int& i0, float& v1, int& i1,
                                     float dd, int k) {
    bool q = dd < v0;
    bool p = dd < v1;
    float nv1 = q ? v0 : (p ? dd : v1);
    int   ni1 = q ? i0 : (p ? k  : i1);
    v1 = nv1; i1 = ni1;
    v0 = q ? dd : v0;
    i0 = q ? k  : i0;
}

// ---------------------------------------------------------------------------
// Prep: codebook norms (round-2/5-identical serial chain) + bf16 hi + sc/2
// ---------------------------------------------------------------------------
__global__ void k_prep_c(const float* __restrict__ cb) {
    int k = blockIdx.x * blockDim.x + threadIdx.x;
    if (k == 0 && blockIdx.x == 0) { g_loss = 0.0; g_nfix = 0; }
    if (k < KCODE) {
        const float* c = cb + (size_t)k * D;
        float s = 0.f;
        #pragma unroll 8
        for (int d = 0; d < D; d++) {
            float x = c[d];
            s += x * x;
            g_ch[k * D + d] = __float2bfloat16(x);
        }
        g_sc[k] = s;
        g_schalf[k] = 0.5f * s;
    }
}

// ---------------------------------------------------------------------------
// Prep: token norms (round-2/5-identical serial chain) + bf16 hi
// ---------------------------------------------------------------------------
__global__ __launch_bounds__(256)
void k_prep_z(const float* __restrict__ z) {
    extern __shared__ float zsm[];
    int tid = threadIdx.x;
    int mbase = blockIdx.x * 128;
    for (int i = tid; i < 128 * (D / 4); i += 256) {
        int m = i / (D / 4), d4 = i % (D / 4);
        float4 v = *(const float4*)(z + (size_t)(mbase + m) * D + d4 * 4);
        *(float4*)(zsm + m * PAD + d4 * 4) = v;
    }
    __syncthreads();
    if (tid < 128) {
        const float* row = zsm + tid * PAD;
        float s = 0.f;
        #pragma unroll 8
        for (int d = 0; d < D; d++) s += row[d] * row[d];
        g_sz[mbase + tid] = s;
    }
    for (int i = tid; i < 128 * D; i += 256) {
        int m = i >> 7, d = i & 127;
        g_zh[(size_t)(mbase + m) * D + d] = __float2bfloat16(zsm[m * PAD + d]);
    }
}

// ---------------------------------------------------------------------------
// Main: single-MMA bf16 distance GEMM + branchless top-2 margin epilogue.
// SMEM: [sc/2 4KB][A 128x272B = 34816][B dbuf 2x34816] = 108544 B -> 2 CTA/SM.
// Rows padded to 272B: ldmatrix rows step 68 words -> banks 4r..4r+3: conflict-free.
// ---------------------------------------------------------------------------
#define ROWB   272
#define SM_SC  0
#define SM_A   4096
#define ATILE  (128 * ROWB)            // 34816
#define SM_B   (SM_A + ATILE)          // 38912 (128-aligned)
#define SM_TOT (SM_B + 2 * ATILE)      // 108544

extern __shared__ char smem[];

__global__ __launch_bounds__(256, 2) void k_mma() {
    uint32_t sb = smem_u32(smem);
    int tid = threadIdx.x, wid = tid >> 5, lane = tid & 31;
    int mbase = blockIdx.x * TILEM;

    // sc/2 table
    for (int i = tid; i < KCODE; i += 256)
        ((float*)smem)[i] = g_schalf[i];

    // A tile (plain stores, loaded once)
    #pragma unroll
    for (int j = 0; j < 8; j++) {
        int i = tid + j * 256;
        int row = i >> 4, c = i & 15;
        *(uint4*)(smem + SM_A + row * ROWB + c * 16) =
            *(const uint4*)((const char*)g_zh + (size_t)(mbase + row) * 256 + c * 16);
    }

    // per-thread fixed B chunk coords (8 chunks of 16B per thread)
    uint32_t bdst[8]; uint32_t bsrc[8];
    #pragma unroll
    for (int j = 0; j < 8; j++) {
        int i = tid + j * 256;
        int row = i >> 4, c = i & 15;
        bdst[j] = row * ROWB + c * 16;
        bsrc[j] = row * 256 + c * 16;
    }

    // prefetch B tile 0 -> buf 0
    #pragma unroll
    for (int j = 0; j < 8; j++)
        cp16(sb + SM_B + bdst[j], (const char*)g_ch + bsrc[j]);
    asm volatile("cp.async.commit_group;");

    // fragment bases
    uint32_t abase = sb + SM_A + (wid * 16 + (lane & 15)) * ROWB + (lane >> 4) * 16;
    uint32_t boff  = (((lane >> 4) & 1) * 8 + (lane & 7)) * ROWB + ((lane >> 3) & 1) * 16;

    int   r0lg = lane & 3;
    float tv0[2], tv1[2]; int ti0[2], ti1[2];
    tv0[0] = tv0[1] = tv1[0] = tv1[1] = 3.4e38f;
    ti0[0] = ti0[1] = ti1[0] = ti1[1] = 0x7fffffff;

    for (int it = 0; it < NITER; it++) {
        if (it + 1 < NITER) {
            const char* src = (const char*)g_ch + (size_t)(it + 1) * 32768;
            uint32_t db = sb + SM_B + ((it + 1) & 1) * ATILE;
            #pragma unroll
            for (int j = 0; j < 8; j++)
                cp16(db + bdst[j], src + bsrc[j]);
            asm volatile("cp.async.commit_group;");
            asm volatile("cp.async.wait_group 1;");
        } else {
            asm volatile("cp.async.wait_group 0;");
        }
        __syncthreads();

        float acc[16][4];
        #pragma unroll
        for (int nt = 0; nt < 16; nt++)
            #pragma unroll
            for (int j = 0; j < 4; j++) acc[nt][j] = 0.f;

        uint32_t bbase = sb + SM_B + (it & 1) * ATILE + boff;

        #pragma unroll
        for (int ks = 0; ks < 8; ks++) {
            uint32_t a[4];
            ldsm_x4(a, abase + ks * 32);
            #pragma unroll
            for (int p = 0; p < 8; p++) {
                uint32_t b[4];
                ldsm_x4(b, bbase + p * (16 * ROWB) + ks * 32);
                mma16816(acc[2 * p],     a, b);
                mma16816(acc[2 * p + 1], a, b + 2);
            }
        }

        // epilogue: dd' = sc/2 - dot ; minimize (argmin-equivalent to dist)
        const float* scs = (const float*)smem;
        #pragma unroll
        for (int nt = 0; nt < 16; nt++) {
            int col = it * TILEN + nt * 8 + 2 * r0lg;
            float s0 = scs[col], s1 = scs[col + 1];
            ins2(tv0[0], ti0[0], tv0[1], ti0[1], s0 - acc[nt][0], col);
            ins2(tv0[0], ti0[0], tv0[1], ti0[1], s1 - acc[nt][1], col + 1);
            ins2(tv1[0], ti1[0], tv1[1], ti1[1], s0 - acc[nt][2], col);
            ins2(tv1[0], ti1[0], tv1[1], ti1[1], s1 - acc[nt][3], col + 1);
        }
        __syncthreads();
    }

    // dump per-thread top-2 (scratch over B buffers)
    float* sv = (float*)(smem + SM_B);
    int*   si = (int*)(smem + SM_B + 8192);
    int r0 = wid * 16 + (lane >> 2), r1 = r0 + 8;
    #pragma unroll
    for (int q = 0; q < 2; q++) {
        sv[r0 * 8 + r0lg * 2 + q] = tv0[q]; si[r0 * 8 + r0lg * 2 + q] = ti0[q];
        sv[r1 * 8 + r0lg * 2 + q] = tv1[q]; si[r1 * 8 + r0lg * 2 + q] = ti1[q];
    }
    __syncthreads();

    if (tid < 128) {
        int row = tid, tok = mbase + row, base = row * 8;
        float bv = 3.4e38f; int bi = 0x7fffffff;
        #pragma unroll
        for (int e = 0; e < 8; e++) {
            float v = sv[base + e]; int ii = si[base + e];
            if (v < bv || (v == bv && ii < bi)) { bv = v; bi = ii; }
        }
        float th = bv + TH_DDP;
        int full = 0, cnt = 0;
        #pragma unroll
        for (int t = 0; t < 4; t++)
            if (sv[base + t * 2 + 1] <= th) full = 1;   // thread's 2nd in window -> maybe hidden 3rd
        #pragma unroll
        for (int e = 0; e < 8; e++)
            if (sv[base + e] <= th) { g_cand[tok * 16 + cnt] = si[base + e]; cnt++; }
        if (cnt <= 1 && !full) {
            g_idx[tok] = bi;
        } else {
            int pos = atomicAdd(&g_nfix, 1);
            g_fixlist[pos] = tok | (cnt << 16) | (full << 31);
        }
    }
}

// ---------------------------------------------------------------------------
// Fixup: exact fp32 reference-sequence distances (validated rounds 2 & 5).
// ---------------------------------------------------------------------------
__global__ __launch_bounds__(256)
void k_fix(const float* __restrict__ z, const float* __restrict__ cb) {
    int gw = (blockIdx.x * 256 + threadIdx.x) >> 5;
    int lane = threadIdx.x & 31;
    int nw = (gridDim.x * 256) >> 5;
    int nf = g_nfix;
    for (int i = gw; i < nf; i += nw) {
        int e = g_fixlist[i];
        int tok = e & 0xffff;
        int cnt = (e >> 16) & 0x1f;
        int full = (e >> 31) & 1;
        float sz = g_sz[tok];
        const float* zr = z + (size_t)tok * D;
        float bv = 3.4e38f; int bi = 0x7fffffff;
        if (!full) {
            if (lane < cnt) {
                int k = g_cand[tok * 16 + lane];
                const float* cr = cb + (size_t)k * D;
                float p = 0.f;
                #pragma unroll 8
                for (int d = 0; d < D; d++) p += zr[d] * cr[d];
                bv = (sz + g_sc[k]) - 2.0f * p;
                bi = k;
            }
        } else {
            for (int k = lane; k < KCODE; k += 32) {
                const float* cr = cb + (size_t)k * D;
                float p = 0.f;
                #pragma unroll 8
                for (int d = 0; d < D; d++) p += zr[d] * cr[d];
                float dd = (sz + g_sc[k]) - 2.0f * p;
                if (dd < bv || (dd == bv && k < bi)) { bv = dd; bi = k; }
            }
        }
        #pragma unroll
        for (int o = 16; o > 0; o >>= 1) {
            float ov = __shfl_down_sync(~0u, bv, o);
            int   oi = __shfl_down_sync(~0u, bi, o);
            if (ov < bv || (ov == bv && oi < bi)) { bv = ov; bi = oi; }
        }
        if (lane == 0) g_idx[tok] = bi;
    }
}

// ---------------------------------------------------------------------------
// Output: gather + STE + loss partials + index slots
// ---------------------------------------------------------------------------
__global__ void k_out(const float* __restrict__ z, const float* __restrict__ cb,
                      float* __restrict__ out, int ND) {
    __shared__ double warpsum[8];
    int e = blockIdx.x * 256 + threadIdx.x;
    double v = 0.0;
    if (e < ND) {
        int n = e >> 7, d = e & 127;
        int idx = g_idx[n];
        float q = cb[(size_t)idx * D + d];
        float zv = z[e];
        float t = q - zv;
        out[e] = zv + t;
        v = (double)(t * t);
        if (d == 0) out[(size_t)ND + 1 + n] = (float)idx;
    }
    #pragma unroll
    for (int o = 16; o > 0; o >>= 1) v += __shfl_down_sync(0xffffffffu, v, o);
    if ((threadIdx.x & 31) == 0) warpsum[threadIdx.x >> 5] = v;
    __syncthreads();
    if (threadIdx.x == 0) {
        double s = 0.0;
        #pragma unroll
        for (int w = 0; w < 8; w++) s += warpsum[w];
        atomicAdd(&g_loss, s);
    }
}

__global__ void k_final(float* __restrict__ out, int ND) {
    if (threadIdx.x == 0 && blockIdx.x == 0) {
        double md = g_loss / (double)ND;
        float m = (float)md;
        out[ND] = m + 0.25f * m;
    }
}

// ---------------------------------------------------------------------------
extern "C" void kernel_launch(void* const* d_in, const int* in_sizes, int n_in,
                              void* d_out, int out_size) {
    const float* z  = (const float*)d_in[0];
    const float* cb = (const float*)d_in[1];
    float* out = (float*)d_out;

    int N = in_sizes[0] / D;
    int K = in_sizes[1] / D;
    int ND = N * D;

    cudaFuncSetAttribute(k_prep_z, cudaFuncAttributeMaxDynamicSharedMemorySize,
                         128 * PAD * (int)sizeof(float));
    cudaFuncSetAttribute(k_mma, cudaFuncAttributeMaxDynamicSharedMemorySize, SM_TOT);

    k_prep_c<<<(K + 255) / 256, 256>>>(cb);
    k_prep_z<<<N / 128, 256, 128 * PAD * sizeof(float)>>>(z);
    k_mma   <<<N / TILEM, 256, SM_TOT>>>();
    k_fix   <<<64, 256>>>(z, cb);
    k_out   <<<(ND + 255) / 256, 256>>>(z, cb, out, ND);
    k_final <<<1, 32>>>(out, ND);
}

// round 12
// speedup vs baseline: 1.5353x; 1.5353x over previous
#include <cuda_runtime.h>
#include <cuda_bf16.h>
#include <cstdint>
#include <math.h>

#define D      128
#define NTOK   32768
#define KCODE  1024
#define TILEM  128
#define TILEN  128
#define NITER  8
#define PAD    132
#define TH_DDP 1.5e-4f   // margin on dd' = sc/2 - dot scale (dist scale: 3e-4)

// ---------------- device scratch ----------------
__device__ __align__(16) __nv_bfloat16 g_zh[NTOK * D];
__device__ __align__(16) __nv_bfloat16 g_ch[KCODE * D];
__device__ float  g_sz[NTOK];
__device__ float  g_sc[KCODE];
__device__ float  g_schalf[KCODE];
__device__ int    g_idx[NTOK];
__device__ int    g_cand[NTOK * 16];
__device__ int    g_fixlist[NTOK];
__device__ int    g_nfix;
__device__ double g_loss;

// ---------------- helpers ----------------
__device__ __forceinline__ uint32_t smem_u32(const void* p) {
    uint32_t a;
    asm("{ .reg .u64 t; cvta.to.shared.u64 t, %1; cvt.u32.u64 %0, t; }" : "=r"(a) : "l"(p));
    return a;
}
__device__ __forceinline__ void ldsm_x4(uint32_t* r, uint32_t a) {
    asm volatile("ldmatrix.sync.aligned.m8n8.x4.shared.b16 {%0,%1,%2,%3}, [%4];"
                 : "=r"(r[0]), "=r"(r[1]), "=r"(r[2]), "=r"(r[3]) : "r"(a));
}
__device__ __forceinline__ void mma16816(float* d, const uint32_t* a, const uint32_t* b) {
    asm volatile("mma.sync.aligned.m16n8k16.row.col.f32.bf16.bf16.f32 "
                 "{%0,%1,%2,%3},{%4,%5,%6,%7},{%8,%9},{%0,%1,%2,%3};"
                 : "+f"(d[0]), "+f"(d[1]), "+f"(d[2]), "+f"(d[3])
                 : "r"(a[0]), "r"(a[1]), "r"(a[2]), "r"(a[3]), "r"(b[0]), "r"(b[1]));
}
__device__ __forceinline__ void cp16(uint32_t dst, const void* src) {
    asm volatile("cp.async.cg.shared.global [%0], [%1], 16;" :: "r"(dst), "l"(src));
}
// branchless top-2 insert (2 FSETP + 6 SEL)
__device__ __forceinline__ void ins2(float& v0, int& i0, float& v1, int& i1,
                                     float dd, int k) {
    bool q = dd < v0;
    bool p = dd < v1;
    float nv1 = q ? v0 : (p ? dd : v1);
    int   ni1 = q ? i0 : (p ? k  : i1);
    v1 = nv1; i1 = ni1;
    v0 = q ? dd : v0;
    i0 = q ? k  : i0;
}

// ---------------------------------------------------------------------------
// Prep: codebook norms (round-2/5-identical serial chain) + bf16 hi + sc/2
// ---------------------------------------------------------------------------
__global__ void k_prep_c(const float* __restrict__ cb) {
    int k = blockIdx.x * blockDim.x + threadIdx.x;
    if (k == 0 && blockIdx.x == 0) { g_loss = 0.0; g_nfix = 0; }
    if (k < KCODE) {
        const float* c = cb + (size_t)k * D;
        float s = 0.f;
        #pragma unroll 8
        for (int d = 0; d < D; d++) {
            float x = c[d];
            s += x * x;
            g_ch[k * D + d] = __float2bfloat16(x);
        }
        g_sc[k] = s;
        g_schalf[k] = 0.5f * s;
    }
}

// ---------------------------------------------------------------------------
// Prep: token norms (round-2/5-identical serial chain) + bf16 hi
// ---------------------------------------------------------------------------
__global__ __launch_bounds__(256)
void k_prep_z(const float* __restrict__ z) {
    extern __shared__ float zsm[];
    int tid = threadIdx.x;
    int mbase = blockIdx.x * 128;
    for (int i = tid; i < 128 * (D / 4); i += 256) {
        int m = i / (D / 4), d4 = i % (D / 4);
        float4 v = *(const float4*)(z + (size_t)(mbase + m) * D + d4 * 4);
        *(float4*)(zsm + m * PAD + d4 * 4) = v;
    }
    __syncthreads();
    if (tid < 128) {
        const float* row = zsm + tid * PAD;
        float s = 0.f;
        #pragma unroll 8
        for (int d = 0; d < D; d++) s += row[d] * row[d];
        g_sz[mbase + tid] = s;
    }
    for (int i = tid; i < 128 * D; i += 256) {
        int m = i >> 7, d = i & 127;
        g_zh[(size_t)(mbase + m) * D + d] = __float2bfloat16(zsm[m * PAD + d]);
    }
}

// ---------------------------------------------------------------------------
// Main: single-MMA bf16 distance GEMM + branchless top-2 margin epilogue.
// N-tile split into two 64-col halves so acc[8][4]=32 regs -> fits 128-reg cap
// at occupancy 2 with NO spills (round-9 post-mortem: (256,2) + acc[16][4]
// spilled to local memory -> 10x regression).
// SMEM: [sc/2 4KB][A 128x272B][B dbuf 2x34816] = 108544 B -> 2 CTA/SM.
// Rows padded to 272B: ldmatrix rows step 68 words -> conflict-free.
// ---------------------------------------------------------------------------
#define ROWB   272
#define SM_SC  0
#define SM_A   4096
#define ATILE  (128 * ROWB)            // 34816
#define SM_B   (SM_A + ATILE)          // 38912 (128-aligned)
#define SM_TOT (SM_B + 2 * ATILE)      // 108544

extern __shared__ char smem[];

__global__ __launch_bounds__(256, 2) void k_mma() {
    uint32_t sb = smem_u32(smem);
    int tid = threadIdx.x, wid = tid >> 5, lane = tid & 31;
    int mbase = blockIdx.x * TILEM;

    // sc/2 table
    for (int i = tid; i < KCODE; i += 256)
        ((float*)smem)[i] = g_schalf[i];

    // A tile (plain stores, loaded once)
    #pragma unroll
    for (int j = 0; j < 8; j++) {
        int i = tid + j * 256;
        int row = i >> 4, c = i & 15;
        *(uint4*)(smem + SM_A + row * ROWB + c * 16) =
            *(const uint4*)((const char*)g_zh + (size_t)(mbase + row) * 256 + c * 16);
    }

    // prefetch B tile 0 -> buf 0 (addresses recomputed, not kept in regs)
    #pragma unroll
    for (int j = 0; j < 8; j++) {
        int i = tid + j * 256;
        int row = i >> 4, c = i & 15;
        cp16(sb + SM_B + row * ROWB + c * 16, (const char*)g_ch + row * 256 + c * 16);
    }
    asm volatile("cp.async.commit_group;");

    // fragment bases
    uint32_t abase = sb + SM_A + (wid * 16 + (lane & 15)) * ROWB + (lane >> 4) * 16;
    uint32_t boff  = (((lane >> 4) & 1) * 8 + (lane & 7)) * ROWB + ((lane >> 3) & 1) * 16;

    int   r0lg = lane & 3;
    float tv0[2], tv1[2]; int ti0[2], ti1[2];
    tv0[0] = tv0[1] = tv1[0] = tv1[1] = 3.4e38f;
    ti0[0] = ti0[1] = ti1[0] = ti1[1] = 0x7fffffff;

    for (int it = 0; it < NITER; it++) {
        if (it + 1 < NITER) {
            const char* src = (const char*)g_ch + (size_t)(it + 1) * 32768;
            uint32_t db = sb + SM_B + ((it + 1) & 1) * ATILE;
            #pragma unroll
            for (int j = 0; j < 8; j++) {
                int i = tid + j * 256;
                int row = i >> 4, c = i & 15;
                cp16(db + row * ROWB + c * 16, src + row * 256 + c * 16);
            }
            asm volatile("cp.async.commit_group;");
            asm volatile("cp.async.wait_group 1;");
        } else {
            asm volatile("cp.async.wait_group 0;");
        }
        __syncthreads();

        uint32_t bbase = sb + SM_B + (it & 1) * ATILE + boff;
        const float* scs = (const float*)smem;

        #pragma unroll
        for (int nh = 0; nh < 2; nh++) {       // two 64-column halves
            float acc[8][4];
            #pragma unroll
            for (int nt = 0; nt < 8; nt++)
                #pragma unroll
                for (int j = 0; j < 4; j++) acc[nt][j] = 0.f;

            #pragma unroll
            for (int ks = 0; ks < 8; ks++) {
                uint32_t a[4];
                ldsm_x4(a, abase + ks * 32);
                #pragma unroll
                for (int q = 0; q < 4; q++) {
                    uint32_t b[4];
                    ldsm_x4(b, bbase + (nh * 4 + q) * (16 * ROWB) + ks * 32);
                    mma16816(acc[2 * q],     a, b);
                    mma16816(acc[2 * q + 1], a, b + 2);
                }
            }

            // epilogue: dd' = sc/2 - dot (argmin-equivalent to dist)
            #pragma unroll
            for (int nt = 0; nt < 8; nt++) {
                int col = it * TILEN + nh * 64 + nt * 8 + 2 * r0lg;
                float s0 = scs[col], s1 = scs[col + 1];
                ins2(tv0[0], ti0[0], tv0[1], ti0[1], s0 - acc[nt][0], col);
                ins2(tv0[0], ti0[0], tv0[1], ti0[1], s1 - acc[nt][1], col + 1);
                ins2(tv1[0], ti1[0], tv1[1], ti1[1], s0 - acc[nt][2], col);
                ins2(tv1[0], ti1[0], tv1[1], ti1[1], s1 - acc[nt][3], col + 1);
            }
        }
        __syncthreads();
    }

    // dump per-thread top-2 (scratch over B buffers)
    float* sv = (float*)(smem + SM_B);
    int*   si = (int*)(smem + SM_B + 8192);
    int r0 = wid * 16 + (lane >> 2), r1 = r0 + 8;
    #pragma unroll
    for (int q = 0; q < 2; q++) {
        sv[r0 * 8 + r0lg * 2 + q] = tv0[q]; si[r0 * 8 + r0lg * 2 + q] = ti0[q];
        sv[r1 * 8 + r0lg * 2 + q] = tv1[q]; si[r1 * 8 + r0lg * 2 + q] = ti1[q];
    }
    __syncthreads();

    if (tid < 128) {
        int row = tid, tok = mbase + row, base = row * 8;
        float bv = 3.4e38f; int bi = 0x7fffffff;
        #pragma unroll
        for (int e = 0; e < 8; e++) {
            float v = sv[base + e]; int ii = si[base + e];
            if (v < bv || (v == bv && ii < bi)) { bv = v; bi = ii; }
        }
        float th = bv + TH_DDP;
        int full = 0, cnt = 0;
        #pragma unroll
        for (int t = 0; t < 4; t++)
            if (sv[base + t * 2 + 1] <= th) full = 1;   // thread's 2nd in window -> maybe hidden 3rd
        #pragma unroll
        for (int e = 0; e < 8; e++)
            if (sv[base + e] <= th) { g_cand[tok * 16 + cnt] = si[base + e]; cnt++; }
        if (cnt <= 1 && !full) {
            g_idx[tok] = bi;
        } else {
            int pos = atomicAdd(&g_nfix, 1);
            g_fixlist[pos] = tok | (cnt << 16) | (full << 31);
        }
    }
}

// ---------------------------------------------------------------------------
// Fixup: exact fp32 reference-sequence distances (validated rounds 2/5/9).
// ---------------------------------------------------------------------------
__global__ __launch_bounds__(256)
void k_fix(const float* __restrict__ z, const float* __restrict__ cb) {
    int gw = (blockIdx.x * 256 + threadIdx.x) >> 5;
    int lane = threadIdx.x & 31;
    int nw = (gridDim.x * 256) >> 5;
    int nf = g_nfix;
    for (int i = gw; i < nf; i += nw) {
        int e = g_fixlist[i];
        int tok = e & 0xffff;
        int cnt = (e >> 16) & 0x1f;
        int full = (e >> 31) & 1;
        float sz = g_sz[tok];
        const float* zr = z + (size_t)tok * D;
        float bv = 3.4e38f; int bi = 0x7fffffff;
        if (!full) {
            if (lane < cnt) {
                int k = g_cand[tok * 16 + lane];
                const float* cr = cb + (size_t)k * D;
                float p = 0.f;
                #pragma unroll 8
                for (int d = 0; d < D; d++) p += zr[d] * cr[d];
                bv = (sz + g_sc[k]) - 2.0f * p;
                bi = k;
            }
        } else {
            for (int k = lane; k < KCODE; k += 32) {
                const float* cr = cb + (size_t)k * D;
                float p = 0.f;
                #pragma unroll 8
                for (int d = 0; d < D; d++) p += zr[d] * cr[d];
                float dd = (sz + g_sc[k]) - 2.0f * p;
                if (dd < bv || (dd == bv && k < bi)) { bv = dd; bi = k; }
            }
        }
        #pragma unroll
        for (int o = 16; o > 0; o >>= 1) {
            float ov = __shfl_down_sync(~0u, bv, o);
            int   oi = __shfl_down_sync(~0u, bi, o);
            if (ov < bv || (ov == bv && oi < bi)) { bv = ov; bi = oi; }
        }
        if (lane == 0) g_idx[tok] = bi;
    }
}

// ---------------------------------------------------------------------------
// Output: gather + STE + loss partials + index slots
// ---------------------------------------------------------------------------
__global__ void k_out(const float* __restrict__ z, const float* __restrict__ cb,
                      float* __restrict__ out, int ND) {
    __shared__ double warpsum[8];
    int e = blockIdx.x * 256 + threadIdx.x;
    double v = 0.0;
    if (e < ND) {
        int n = e >> 7, d = e & 127;
        int idx = g_idx[n];
        float q = cb[(size_t)idx * D + d];
        float zv = z[e];
        float t = q - zv;
        out[e] = zv + t;
        v = (double)(t * t);
        if (d == 0) out[(size_t)ND + 1 + n] = (float)idx;
    }
    #pragma unroll
    for (int o = 16; o > 0; o >>= 1) v += __shfl_down_sync(0xffffffffu, v, o);
    if ((threadIdx.x & 31) == 0) warpsum[threadIdx.x >> 5] = v;
    __syncthreads();
    if (threadIdx.x == 0) {
        double s = 0.0;
        #pragma unroll
        for (int w = 0; w < 8; w++) s += warpsum[w];
        atomicAdd(&g_loss, s);
    }
}

__global__ void k_final(float* __restrict__ out, int ND) {
    if (threadIdx.x == 0 && blockIdx.x == 0) {
        double md = g_loss / (double)ND;
        float m = (float)md;
        out[ND] = m + 0.25f * m;
    }
}

// ---------------------------------------------------------------------------
extern "C" void kernel_launch(void* const* d_in, const int* in_sizes, int n_in,
                              void* d_out, int out_size) {
    const float* z  = (const float*)d_in[0];
    const float* cb = (const float*)d_in[1];
    float* out = (float*)d_out;

    int N = in_sizes[0] / D;
    int K = in_sizes[1] / D;
    int ND = N * D;

    cudaFuncSetAttribute(k_prep_z, cudaFuncAttributeMaxDynamicSharedMemorySize,
                         128 * PAD * (int)sizeof(float));
    cudaFuncSetAttribute(k_mma, cudaFuncAttributeMaxDynamicSharedMemorySize, SM_TOT);

    k_prep_c<<<(K + 255) / 256, 256>>>(cb);
    k_prep_z<<<N / 128, 256, 128 * PAD * sizeof(float)>>>(z);
    k_mma   <<<N / TILEM, 256, SM_TOT>>>();
    k_fix   <<<64, 256>>>(z, cb);
    k_out   <<<(ND + 255) / 256, 256>>>(z, cb, out, ND);
    k_final <<<1, 32>>>(out, ND);
}

// round 14
// speedup vs baseline: 1.5799x; 1.0291x over previous
#include <cuda_runtime.h>
#include <cuda_bf16.h>
#include <cstdint>
#include <math.h>

#define D      128
#define NTOK   32768
#define KCODE  1024
#define TILEM  128
#define TILEN  128
#define NITER  8
#define PAD    132
#define TH_DDP 1.5e-4f   // margin on dd' = sc/2 - dot scale (dist scale: 3e-4)

// ---------------- device scratch ----------------
__device__ __align__(16) __nv_bfloat16 g_zh[NTOK * D];
__device__ __align__(16) __nv_bfloat16 g_ch[KCODE * D];
__device__ float  g_sz[NTOK];
__device__ float  g_sc[KCODE];
__device__ float  g_schalf[KCODE];
__device__ int    g_idx[NTOK];
__device__ int    g_cand[NTOK * 16];
__device__ int    g_fixlist[NTOK];
__device__ int    g_nfix;
__device__ double g_loss;

// ---------------- helpers ----------------
__device__ __forceinline__ uint32_t smem_u32(const void* p) {
    uint32_t a;
    asm("{ .reg .u64 t; cvta.to.shared.u64 t, %1; cvt.u32.u64 %0, t; }" : "=r"(a) : "l"(p));
    return a;
}
__device__ __forceinline__ void ldsm_x4(uint32_t* r, uint32_t a) {
    asm volatile("ldmatrix.sync.aligned.m8n8.x4.shared.b16 {%0,%1,%2,%3}, [%4];"
                 : "=r"(r[0]), "=r"(r[1]), "=r"(r[2]), "=r"(r[3]) : "r"(a));
}
__device__ __forceinline__ void mma16816(float* d, const uint32_t* a, const uint32_t* b) {
    asm volatile("mma.sync.aligned.m16n8k16.row.col.f32.bf16.bf16.f32 "
                 "{%0,%1,%2,%3},{%4,%5,%6,%7},{%8,%9},{%0,%1,%2,%3};"
                 : "+f"(d[0]), "+f"(d[1]), "+f"(d[2]), "+f"(d[3])
                 : "r"(a[0]), "r"(a[1]), "r"(a[2]), "r"(a[3]), "r"(b[0]), "r"(b[1]));
}
__device__ __forceinline__ void cp16(uint32_t dst, const void* src) {
    asm volatile("cp.async.cg.shared.global [%0], [%1], 16;" :: "r"(dst), "l"(src));
}
// branchless top-2 insert (2 FSETP + 6 SEL)
__device__ __forceinline__ void ins2(float& v0, int& i0, float& v1, int& i1,
                                     float dd, int k) {
    bool q = dd < v0;
    bool p = dd < v1;
    float nv1 = q ? v0 : (p ? dd : v1);
    int   ni1 = q ? i0 : (p ? k  : i1);
    v1 = nv1; i1 = ni1;
    v0 = q ? dd : v0;
    i0 = q ? k  : i0;
}

// ---------------------------------------------------------------------------
// Prep: codebook norms (round-2/5-identical serial chain) + bf16 hi + sc/2
// ---------------------------------------------------------------------------
__global__ void k_prep_c(const float* __restrict__ cb) {
    int k = blockIdx.x * blockDim.x + threadIdx.x;
    if (k == 0 && blockIdx.x == 0) { g_loss = 0.0; g_nfix = 0; }
    if (k < KCODE) {
        const float* c = cb + (size_t)k * D;
        float s = 0.f;
        #pragma unroll 8
        for (int d = 0; d < D; d++) {
            float x = c[d];
            s += x * x;
            g_ch[k * D + d] = __float2bfloat16(x);
        }
        g_sc[k] = s;
        g_schalf[k] = 0.5f * s;
    }
}

// ---------------------------------------------------------------------------
// Prep: token norms (round-2/5-identical serial chain) + bf16 hi
// ---------------------------------------------------------------------------
__global__ __launch_bounds__(256)
void k_prep_z(const float* __restrict__ z) {
    extern __shared__ float zsm[];
    int tid = threadIdx.x;
    int mbase = blockIdx.x * 128;
    for (int i = tid; i < 128 * (D / 4); i += 256) {
        int m = i / (D / 4), d4 = i % (D / 4);
        float4 v = *(const float4*)(z + (size_t)(mbase + m) * D + d4 * 4);
        *(float4*)(zsm + m * PAD + d4 * 4) = v;
    }
    __syncthreads();
    if (tid < 128) {
        const float* row = zsm + tid * PAD;
        float s = 0.f;
        #pragma unroll 8
        for (int d = 0; d < D; d++) s += row[d] * row[d];
        g_sz[mbase + tid] = s;
    }
    for (int i = tid; i < 128 * D; i += 256) {
        int m = i >> 7, d = i & 127;
        g_zh[(size_t)(mbase + m) * D + d] = __float2bfloat16(zsm[m * PAD + d]);
    }
}

// ---------------------------------------------------------------------------
// Main: single-MMA bf16 distance GEMM + branchless top-2 margin epilogue.
// SINGLE-VARIABLE CHANGE vs round 12: __launch_bounds__(256, 2) -> (256, 1).
// Round-9/12 post-mortem: the (256,2) 128-reg cap made ptxas spill inside the
// MMA mainloop (2387 us; acc-split partial fix -> 1555 us). Occupancy 1 with
// free regs (255) is the round-5-validated regime (239.7 us with 3x the work).
// SMEM: [sc/2 4KB][A 128x272B][B dbuf 2x34816] = 108544 B.
// Rows padded to 272B: ldmatrix rows step 68 words -> conflict-free.
// ---------------------------------------------------------------------------
#define ROWB   272
#define SM_SC  0
#define SM_A   4096
#define ATILE  (128 * ROWB)            // 34816
#define SM_B   (SM_A + ATILE)          // 38912 (128-aligned)
#define SM_TOT (SM_B + 2 * ATILE)      // 108544

extern __shared__ char smem[];

__global__ __launch_bounds__(256, 1) void k_mma() {
    uint32_t sb = smem_u32(smem);
    int tid = threadIdx.x, wid = tid >> 5, lane = tid & 31;
    int mbase = blockIdx.x * TILEM;

    // sc/2 table
    for (int i = tid; i < KCODE; i += 256)
        ((float*)smem)[i] = g_schalf[i];

    // A tile (plain stores, loaded once)
    #pragma unroll
    for (int j = 0; j < 8; j++) {
        int i = tid + j * 256;
        int row = i >> 4, c = i & 15;
        *(uint4*)(smem + SM_A + row * ROWB + c * 16) =
            *(const uint4*)((const char*)g_zh + (size_t)(mbase + row) * 256 + c * 16);
    }

    // prefetch B tile 0 -> buf 0
    #pragma unroll
    for (int j = 0; j < 8; j++) {
        int i = tid + j * 256;
        int row = i >> 4, c = i & 15;
        cp16(sb + SM_B + row * ROWB + c * 16, (const char*)g_ch + row * 256 + c * 16);
    }
    asm volatile("cp.async.commit_group;");

    // fragment bases
    uint32_t abase = sb + SM_A + (wid * 16 + (lane & 15)) * ROWB + (lane >> 4) * 16;
    uint32_t boff  = (((lane >> 4) & 1) * 8 + (lane & 7)) * ROWB + ((lane >> 3) & 1) * 16;

    int   r0lg = lane & 3;
    float tv0[2], tv1[2]; int ti0[2], ti1[2];
    tv0[0] = tv0[1] = tv1[0] = tv1[1] = 3.4e38f;
    ti0[0] = ti0[1] = ti1[0] = ti1[1] = 0x7fffffff;

    for (int it = 0; it < NITER; it++) {
        if (it + 1 < NITER) {
            const char* src = (const char*)g_ch + (size_t)(it + 1) * 32768;
            uint32_t db = sb + SM_B + ((it + 1) & 1) * ATILE;
            #pragma unroll
            for (int j = 0; j < 8; j++) {
                int i = tid + j * 256;
                int row = i >> 4, c = i & 15;
                cp16(db + row * ROWB + c * 16, src + row * 256 + c * 16);
            }
            asm volatile("cp.async.commit_group;");
            asm volatile("cp.async.wait_group 1;");
        } else {
            asm volatile("cp.async.wait_group 0;");
        }
        __syncthreads();

        uint32_t bbase = sb + SM_B + (it & 1) * ATILE + boff;
        const float* scs = (const float*)smem;

        #pragma unroll
        for (int nh = 0; nh < 2; nh++) {       // two 64-column halves
            float acc[8][4];
            #pragma unroll
            for (int nt = 0; nt < 8; nt++)
                #pragma unroll
                for (int j = 0; j < 4; j++) acc[nt][j] = 0.f;

            #pragma unroll
            for (int ks = 0; ks < 8; ks++) {
                uint32_t a[4];
                ldsm_x4(a, abase + ks * 32);
                #pragma unroll
                for (int q = 0; q < 4; q++) {
                    uint32_t b[4];
                    ldsm_x4(b, bbase + (nh * 4 + q) * (16 * ROWB) + ks * 32);
                    mma16816(acc[2 * q],     a, b);
                    mma16816(acc[2 * q + 1], a, b + 2);
                }
            }

            // epilogue: dd' = sc/2 - dot (argmin-equivalent to dist)
            #pragma unroll
            for (int nt = 0; nt < 8; nt++) {
                int col = it * TILEN + nh * 64 + nt * 8 + 2 * r0lg;
                float s0 = scs[col], s1 = scs[col + 1];
                ins2(tv0[0], ti0[0], tv0[1], ti0[1], s0 - acc[nt][0], col);
                ins2(tv0[0], ti0[0], tv0[1], ti0[1], s1 - acc[nt][1], col + 1);
                ins2(tv1[0], ti1[0], tv1[1], ti1[1], s0 - acc[nt][2], col);
                ins2(tv1[0], ti1[0], tv1[1], ti1[1], s1 - acc[nt][3], col + 1);
            }
        }
        __syncthreads();
    }

    // dump per-thread top-2 (scratch over B buffers)
    float* sv = (float*)(smem + SM_B);
    int*   si = (int*)(smem + SM_B + 8192);
    int r0 = wid * 16 + (lane >> 2), r1 = r0 + 8;
    #pragma unroll
    for (int q = 0; q < 2; q++) {
        sv[r0 * 8 + r0lg * 2 + q] = tv0[q]; si[r0 * 8 + r0lg * 2 + q] = ti0[q];
        sv[r1 * 8 + r0lg * 2 + q] = tv1[q]; si[r1 * 8 + r0lg * 2 + q] = ti1[q];
    }
    __syncthreads();

    if (tid < 128) {
        int row = tid, tok = mbase + row, base = row * 8;
        float bv = 3.4e38f; int bi = 0x7fffffff;
        #pragma unroll
        for (int e = 0; e < 8; e++) {
            float v = sv[base + e]; int ii = si[base + e];
            if (v < bv || (v == bv && ii < bi)) { bv = v; bi = ii; }
        }
        float th = bv + TH_DDP;
        int full = 0, cnt = 0;
        #pragma unroll
        for (int t = 0; t < 4; t++)
            if (sv[base + t * 2 + 1] <= th) full = 1;   // thread's 2nd in window -> maybe hidden 3rd
        #pragma unroll
        for (int e = 0; e < 8; e++)
            if (sv[base + e] <= th) { g_cand[tok * 16 + cnt] = si[base + e]; cnt++; }
        if (cnt <= 1 && !full) {
            g_idx[tok] = bi;
        } else {
            int pos = atomicAdd(&g_nfix, 1);
            g_fixlist[pos] = tok | (cnt << 16) | (full << 31);
        }
    }
}

// ---------------------------------------------------------------------------
// Fixup: exact fp32 reference-sequence distances (validated rounds 2/5/9/12).
// ---------------------------------------------------------------------------
__global__ __launch_bounds__(256)
void k_fix(const float* __restrict__ z, const float* __restrict__ cb) {
    int gw = (blockIdx.x * 256 + threadIdx.x) >> 5;
    int lane = threadIdx.x & 31;
    int nw = (gridDim.x * 256) >> 5;
    int nf = g_nfix;
    for (int i = gw; i < nf; i += nw) {
        int e = g_fixlist[i];
        int tok = e & 0xffff;
        int cnt = (e >> 16) & 0x1f;
        int full = (e >> 31) & 1;
        float sz = g_sz[tok];
        const float* zr = z + (size_t)tok * D;
        float bv = 3.4e38f; int bi = 0x7fffffff;
        if (!full) {
            if (lane < cnt) {
                int k = g_cand[tok * 16 + lane];
                const float* cr = cb + (size_t)k * D;
                float p = 0.f;
                #pragma unroll 8
                for (int d = 0; d < D; d++) p += zr[d] * cr[d];
                bv = (sz + g_sc[k]) - 2.0f * p;
                bi = k;
            }
        } else {
            for (int k = lane; k < KCODE; k += 32) {
                const float* cr = cb + (size_t)k * D;
                float p = 0.f;
                #pragma unroll 8
                for (int d = 0; d < D; d++) p += zr[d] * cr[d];
                float dd = (sz + g_sc[k]) - 2.0f * p;
                if (dd < bv || (dd == bv && k < bi)) { bv = dd; bi = k; }
            }
        }
        #pragma unroll
        for (int o = 16; o > 0; o >>= 1) {
            float ov = __shfl_down_sync(~0u, bv, o);
            int   oi = __shfl_down_sync(~0u, bi, o);
            if (ov < bv || (ov == bv && oi < bi)) { bv = ov; bi = oi; }
        }
        if (lane == 0) g_idx[tok] = bi;
    }
}

// ---------------------------------------------------------------------------
// Output: gather + STE + loss partials + index slots
// ---------------------------------------------------------------------------
__global__ void k_out(const float* __restrict__ z, const float* __restrict__ cb,
                      float* __restrict__ out, int ND) {
    __shared__ double warpsum[8];
    int e = blockIdx.x * 256 + threadIdx.x;
    double v = 0.0;
    if (e < ND) {
        int n = e >> 7, d = e & 127;
        int idx = g_idx[n];
        float q = cb[(size_t)idx * D + d];
        float zv = z[e];
        float t = q - zv;
        out[e] = zv + t;
        v = (double)(t * t);
        if (d == 0) out[(size_t)ND + 1 + n] = (float)idx;
    }
    #pragma unroll
    for (int o = 16; o > 0; o >>= 1) v += __shfl_down_sync(0xffffffffu, v, o);
    if ((threadIdx.x & 31) == 0) warpsum[threadIdx.x >> 5] = v;
    __syncthreads();
    if (threadIdx.x == 0) {
        double s = 0.0;
        #pragma unroll
        for (int w = 0; w < 8; w++) s += warpsum[w];
        atomicAdd(&g_loss, s);
    }
}

__global__ void k_final(float* __restrict__ out, int ND) {
    if (threadIdx.x == 0 && blockIdx.x == 0) {
        double md = g_loss / (double)ND;
        float m = (float)md;
        out[ND] = m + 0.25f * m;
    }
}

// ---------------------------------------------------------------------------
extern "C" void kernel_launch(void* const* d_in, const int* in_sizes, int n_in,
                              void* d_out, int out_size) {
    const float* z  = (const float*)d_in[0];
    const float* cb = (const float*)d_in[1];
    float* out = (float*)d_out;

    int N = in_sizes[0] / D;
    int K = in_sizes[1] / D;
    int ND = N * D;

    cudaFuncSetAttribute(k_prep_z, cudaFuncAttributeMaxDynamicSharedMemorySize,
                         128 * PAD * (int)sizeof(float));
    cudaFuncSetAttribute(k_mma, cudaFuncAttributeMaxDynamicSharedMemorySize, SM_TOT);

    k_prep_c<<<(K + 255) / 256, 256>>>(cb);
    k_prep_z<<<N / 128, 256, 128 * PAD * sizeof(float)>>>(z);
    k_mma   <<<N / TILEM, 256, SM_TOT>>>();
    k_fix   <<<64, 256>>>(z, cb);
    k_out   <<<(ND + 255) / 256, 256>>>(z, cb, out, ND);
    k_final <<<1, 32>>>(out, ND);
}